// round 8
// baseline (speedup 1.0000x reference)
#include <cuda_runtime.h>
#include <cstdint>

// ParallelTransport: out[b,i,j,:,:] = 6-term Taylor exp of
//   M[b,i,j] = sum_d (x[b,j,d]-x[b,i,d]) * A[b,j,d,:,:]
//
// R2: packed f32x2 FMA (FFMA2) everywhere.
//   Phase 1: M_tile[256 x 64] = Y[256 x 512] @ A_j[512 x 64], thread tile 8x8,
//            rows packed in f32x2 (X stored transposed), A pre-duplicated (a,a).
//   Phase 2: per-8x8 Taylor, columns packed in f32x2.

#define SS       512
#define DD       512
#define TILE_I   256
#define DK       32
#define THREADS  256
#define XST      260          // floats per Xs row  (260*4 = 1040 = 65*16)
#define AST2     66           // u64 per As2 row    (66*8  = 528, 16B-mult)
#define MST      68           // floats per Ms row  (68*4  = 272 = 17*16)

#define XS_BYTES  (DK * XST * 4)          // 33280
#define AS2_OFF   XS_BYTES
#define AS2_BYTES (DK * AST2 * 8)         // 16896
#define MS_BYTES  (TILE_I * MST * 4)      // 69632
#define DYN_SMEM  (MS_BYTES)              // >= XS_BYTES+AS2_BYTES (50176)

typedef unsigned long long u64;

#define FMA2(D,A,B,C) asm("fma.rn.f32x2 %0,%1,%2,%3;" : "=l"(D) : "l"(A), "l"(B), "l"(C))
#define MUL2(D,A,B)   asm("mul.rn.f32x2 %0,%1,%2;"    : "=l"(D) : "l"(A), "l"(B))
#define ADD2(D,A,B)   asm("add.rn.f32x2 %0,%1,%2;"    : "=l"(D) : "l"(A), "l"(B))

__device__ __forceinline__ u64 pk2(float a, float b) {
    u64 r; asm("mov.b64 %0,{%1,%2};" : "=l"(r) : "f"(a), "f"(b)); return r;
}
__device__ __forceinline__ void upk2(float& a, float& b, u64 v) {
    asm("mov.b64 {%0,%1},%2;" : "=f"(a), "=f"(b) : "l"(v));
}

__global__ __launch_bounds__(THREADS, 2)
void pt_kernel(const float* __restrict__ x,
               const float* __restrict__ A,
               float* __restrict__ out)
{
    extern __shared__ __align__(16) char smraw[];
    float (*Xs)[XST]  = reinterpret_cast<float (*)[XST]>(smraw);
    u64   (*As2)[AST2] = reinterpret_cast<u64 (*)[AST2]>(smraw + AS2_OFF);
    float (*Ms)[MST]  = reinterpret_cast<float (*)[MST]>(smraw);

    const int blk = blockIdx.x;
    const int it  = blk & 1;
    const int j   = (blk >> 1) & (SS - 1);
    const int b   = blk >> 10;
    const int i0  = it * TILE_I;

    const int tid = threadIdx.x;
    const int klg = tid & 7;     // 0..7  -> kl columns klg*8 .. +7
    const int ig  = tid >> 3;    // 0..31 -> rows ig*8 .. +7

    const float* Xb      = x + (size_t)b * SS * DD;
    const float* xi_base = Xb + (size_t)i0 * DD;
    const float* xj      = Xb + (size_t)j * DD;
    const float* Ab      = A + ((size_t)b * SS + j) * DD * 64;

    u64 acc2[4][8];              // row-pair (2*ii2, 2*ii2+1) x col c
#pragma unroll
    for (int ii2 = 0; ii2 < 4; ii2++)
#pragma unroll
        for (int c = 0; c < 8; c++) acc2[ii2][c] = 0ULL;

    for (int dk = 0; dk < DD; dk += DK) {
        // ---- stage A chunk, duplicated (a,a): A[b,j, dk..dk+DK, 0..63]
#pragma unroll
        for (int f = tid; f < DK * 16; f += THREADS) {      // 512 float4 -> 2/thread
            int d = f >> 4, q = f & 15;
            float4 v = *(const float4*)(Ab + (size_t)(dk + d) * 64 + q * 4);
            As2[d][q * 4 + 0] = pk2(v.x, v.x);
            As2[d][q * 4 + 1] = pk2(v.y, v.y);
            As2[d][q * 4 + 2] = pk2(v.z, v.z);
            As2[d][q * 4 + 3] = pk2(v.w, v.w);
        }
        // ---- stage X chunk TRANSPOSED with x_j - x_i applied: Xs[d][row]
#pragma unroll
        for (int f = tid; f < TILE_I * (DK / 4); f += THREADS) {  // 2048 -> 8/thread
            int row = f >> 3, q = f & 7;
            float4 vi = *(const float4*)(xi_base + (size_t)row * DD + dk + q * 4);
            float4 vj = *(const float4*)(xj + dk + q * 4);
            Xs[q * 4 + 0][row] = vj.x - vi.x;
            Xs[q * 4 + 1][row] = vj.y - vi.y;
            Xs[q * 4 + 2][row] = vj.z - vi.z;
            Xs[q * 4 + 3][row] = vj.w - vi.w;
        }
        __syncthreads();

#pragma unroll 2
        for (int d = 0; d < DK; d++) {
            // 8 rows -> 4 packed row-pairs (natural pairs from LDS.128)
            ulonglong2 xA = *(const ulonglong2*)&Xs[d][ig * 8];
            ulonglong2 xB = *(const ulonglong2*)&Xs[d][ig * 8 + 4];
            u64 xp[4] = {xA.x, xA.y, xB.x, xB.y};
            // 8 duplicated A operands (4 x LDS.128)
            ulonglong2 a01 = *(const ulonglong2*)&As2[d][klg * 8 + 0];
            ulonglong2 a23 = *(const ulonglong2*)&As2[d][klg * 8 + 2];
            ulonglong2 a45 = *(const ulonglong2*)&As2[d][klg * 8 + 4];
            ulonglong2 a67 = *(const ulonglong2*)&As2[d][klg * 8 + 6];
            u64 ap[8] = {a01.x, a01.y, a23.x, a23.y, a45.x, a45.y, a67.x, a67.y};
#pragma unroll
            for (int ii2 = 0; ii2 < 4; ii2++)
#pragma unroll
                for (int c = 0; c < 8; c++)
                    FMA2(acc2[ii2][c], xp[ii2], ap[c], acc2[ii2][c]);
        }
        __syncthreads();
    }

    // ---- dump M tile into shared (aliases Xs/As2; loop-final sync covers WAR)
#pragma unroll
    for (int ii2 = 0; ii2 < 4; ii2++) {
        float lo[8], hi[8];
#pragma unroll
        for (int c = 0; c < 8; c++) upk2(lo[c], hi[c], acc2[ii2][c]);
        int r0 = ig * 8 + 2 * ii2;
        *(float4*)&Ms[r0][klg * 8]         = make_float4(lo[0], lo[1], lo[2], lo[3]);
        *(float4*)&Ms[r0][klg * 8 + 4]     = make_float4(lo[4], lo[5], lo[6], lo[7]);
        *(float4*)&Ms[r0 + 1][klg * 8]     = make_float4(hi[0], hi[1], hi[2], hi[3]);
        *(float4*)&Ms[r0 + 1][klg * 8 + 4] = make_float4(hi[4], hi[5], hi[6], hi[7]);
    }
    __syncthreads();

    // ---- Taylor: 8 lanes per 8x8 matrix, one row per lane, 8 passes, f32x2
    const int r     = tid & 7;
    const int mbase = tid >> 3;   // 0..31

    const float invn[7] = {0.f, 1.f, 0.5f, 1.f / 3.f, 0.25f, 0.2f, 1.f / 6.f};

#pragma unroll 1
    for (int p = 0; p < 8; p++) {
        const int m = p * 32 + mbase;

        // full M, rows k, columns packed in pairs
        u64 Mg[8][4];
#pragma unroll
        for (int k = 0; k < 8; k++) {
            ulonglong2 t0 = *(const ulonglong2*)&Ms[m][k * 8];
            ulonglong2 t1 = *(const ulonglong2*)&Ms[m][k * 8 + 4];
            Mg[k][0] = t0.x; Mg[k][1] = t0.y; Mg[k][2] = t1.x; Mg[k][3] = t1.y;
        }
        // own row r: current power P and running result
        u64 P[4], res[4];
        {
            ulonglong2 t0 = *(const ulonglong2*)&Ms[m][r * 8];
            ulonglong2 t1 = *(const ulonglong2*)&Ms[m][r * 8 + 4];
            P[0] = t0.x; P[1] = t0.y; P[2] = t1.x; P[3] = t1.y;
        }
#pragma unroll
        for (int c2 = 0; c2 < 4; c2++) res[c2] = P[c2];

#pragma unroll
        for (int n = 2; n <= 6; n++) {
            float ps[8];
#pragma unroll
            for (int c2 = 0; c2 < 4; c2++) upk2(ps[2 * c2], ps[2 * c2 + 1], P[c2]);
            u64 nw[4] = {0ULL, 0ULL, 0ULL, 0ULL};
#pragma unroll
            for (int k = 0; k < 8; k++) {
                u64 s2 = pk2(ps[k], ps[k]);
#pragma unroll
                for (int c2 = 0; c2 < 4; c2++)
                    FMA2(nw[c2], s2, Mg[k][c2], nw[c2]);
            }
            uint32_t ub = __float_as_uint(invn[n]);
            u64 sc2 = (u64)ub | ((u64)ub << 32);
#pragma unroll
            for (int c2 = 0; c2 < 4; c2++) {
                MUL2(nw[c2], nw[c2], sc2);
                P[c2] = nw[c2];
                ADD2(res[c2], res[c2], nw[c2]);
            }
        }

        float fr[8];
#pragma unroll
        for (int c2 = 0; c2 < 4; c2++) upk2(fr[2 * c2], fr[2 * c2 + 1], res[c2]);
#pragma unroll
        for (int c = 0; c < 8; c++) fr[c] += (c == r) ? 1.0f : 0.0f;   // identity

        size_t off = (((size_t)b * SS + (i0 + m)) * SS + j) * 64 + (size_t)r * 8;
        *(float4*)(out + off)     = make_float4(fr[0], fr[1], fr[2], fr[3]);
        *(float4*)(out + off + 4) = make_float4(fr[4], fr[5], fr[6], fr[7]);
    }
}

extern "C" void kernel_launch(void* const* d_in, const int* in_sizes, int n_in,
                              void* d_out, int out_size)
{
    const float* x = (const float*)d_in[0];   // [4,512,512]
    const float* A = (const float*)d_in[1];   // [4,512,512,8,8]
    float* out = (float*)d_out;               // [4,512,512,8,8]
    (void)in_sizes; (void)n_in; (void)out_size;

    cudaFuncSetAttribute(pt_kernel, cudaFuncAttributeMaxDynamicSharedMemorySize, DYN_SMEM);

    dim3 grid(4 * 512 * 2);   // (b, j, i-tile), i-tile fastest
    dim3 block(THREADS);
    pt_kernel<<<grid, block, DYN_SMEM>>>(x, A, out);
}

// round 9
// speedup vs baseline: 1.0028x; 1.0028x over previous
#include <cuda_runtime.h>
#include <cstdint>

// ParallelTransport: out[b,i,j,:,:] = 6-term Taylor exp of
//   M[b,i,j] = sum_d (x[b,j,d]-x[b,i,d]) * A[b,j,d,:,:]
//
// R2: packed f32x2 FMA (FFMA2) everywhere.
//   Phase 1: M_tile[256 x 64] = Y[256 x 512] @ A_j[512 x 64], thread tile 8x8,
//            rows packed in f32x2 (X stored transposed), A pre-duplicated (a,a).
//   Phase 2: per-8x8 Taylor, columns packed in f32x2.

#define SS       512
#define DD       512
#define TILE_I   256
#define DK       32
#define THREADS  256
#define XST      260          // floats per Xs row  (260*4 = 1040 = 65*16)
#define AST2     66           // u64 per As2 row    (66*8  = 528, 16B-mult)
#define MST      68           // floats per Ms row  (68*4  = 272 = 17*16)

#define XS_BYTES  (DK * XST * 4)          // 33280
#define AS2_OFF   XS_BYTES
#define AS2_BYTES (DK * AST2 * 8)         // 16896
#define MS_BYTES  (TILE_I * MST * 4)      // 69632
#define DYN_SMEM  (MS_BYTES)              // >= XS_BYTES+AS2_BYTES (50176)

typedef unsigned long long u64;

#define FMA2(D,A,B,C) asm("fma.rn.f32x2 %0,%1,%2,%3;" : "=l"(D) : "l"(A), "l"(B), "l"(C))
#define MUL2(D,A,B)   asm("mul.rn.f32x2 %0,%1,%2;"    : "=l"(D) : "l"(A), "l"(B))
#define ADD2(D,A,B)   asm("add.rn.f32x2 %0,%1,%2;"    : "=l"(D) : "l"(A), "l"(B))

__device__ __forceinline__ u64 pk2(float a, float b) {
    u64 r; asm("mov.b64 %0,{%1,%2};" : "=l"(r) : "f"(a), "f"(b)); return r;
}
__device__ __forceinline__ void upk2(float& a, float& b, u64 v) {
    asm("mov.b64 {%0,%1},%2;" : "=f"(a), "=f"(b) : "l"(v));
}

__global__ __launch_bounds__(THREADS, 2)
void pt_kernel(const float* __restrict__ x,
               const float* __restrict__ A,
               float* __restrict__ out)
{
    extern __shared__ __align__(16) char smraw[];
    float (*Xs)[XST]  = reinterpret_cast<float (*)[XST]>(smraw);
    u64   (*As2)[AST2] = reinterpret_cast<u64 (*)[AST2]>(smraw + AS2_OFF);
    float (*Ms)[MST]  = reinterpret_cast<float (*)[MST]>(smraw);

    const int blk = blockIdx.x;
    const int it  = blk & 1;
    const int j   = (blk >> 1) & (SS - 1);
    const int b   = blk >> 10;
    const int i0  = it * TILE_I;

    const int tid = threadIdx.x;
    const int klg = tid & 7;     // 0..7  -> kl columns klg*8 .. +7
    const int ig  = tid >> 3;    // 0..31 -> rows ig*8 .. +7

    const float* Xb      = x + (size_t)b * SS * DD;
    const float* xi_base = Xb + (size_t)i0 * DD;
    const float* xj      = Xb + (size_t)j * DD;
    const float* Ab      = A + ((size_t)b * SS + j) * DD * 64;

    u64 acc2[4][8];              // row-pair (2*ii2, 2*ii2+1) x col c
#pragma unroll
    for (int ii2 = 0; ii2 < 4; ii2++)
#pragma unroll
        for (int c = 0; c < 8; c++) acc2[ii2][c] = 0ULL;

    for (int dk = 0; dk < DD; dk += DK) {
        // ---- stage A chunk, duplicated (a,a): A[b,j, dk..dk+DK, 0..63]
#pragma unroll
        for (int f = tid; f < DK * 16; f += THREADS) {      // 512 float4 -> 2/thread
            int d = f >> 4, q = f & 15;
            float4 v = *(const float4*)(Ab + (size_t)(dk + d) * 64 + q * 4);
            As2[d][q * 4 + 0] = pk2(v.x, v.x);
            As2[d][q * 4 + 1] = pk2(v.y, v.y);
            As2[d][q * 4 + 2] = pk2(v.z, v.z);
            As2[d][q * 4 + 3] = pk2(v.w, v.w);
        }
        // ---- stage X chunk TRANSPOSED with x_j - x_i applied: Xs[d][row]
#pragma unroll
        for (int f = tid; f < TILE_I * (DK / 4); f += THREADS) {  // 2048 -> 8/thread
            int row = f >> 3, q = f & 7;
            float4 vi = *(const float4*)(xi_base + (size_t)row * DD + dk + q * 4);
            float4 vj = *(const float4*)(xj + dk + q * 4);
            Xs[q * 4 + 0][row] = vj.x - vi.x;
            Xs[q * 4 + 1][row] = vj.y - vi.y;
            Xs[q * 4 + 2][row] = vj.z - vi.z;
            Xs[q * 4 + 3][row] = vj.w - vi.w;
        }
        __syncthreads();

#pragma unroll 2
        for (int d = 0; d < DK; d++) {
            // 8 rows -> 4 packed row-pairs (natural pairs from LDS.128)
            ulonglong2 xA = *(const ulonglong2*)&Xs[d][ig * 8];
            ulonglong2 xB = *(const ulonglong2*)&Xs[d][ig * 8 + 4];
            u64 xp[4] = {xA.x, xA.y, xB.x, xB.y};
            // 8 duplicated A operands (4 x LDS.128)
            ulonglong2 a01 = *(const ulonglong2*)&As2[d][klg * 8 + 0];
            ulonglong2 a23 = *(const ulonglong2*)&As2[d][klg * 8 + 2];
            ulonglong2 a45 = *(const ulonglong2*)&As2[d][klg * 8 + 4];
            ulonglong2 a67 = *(const ulonglong2*)&As2[d][klg * 8 + 6];
            u64 ap[8] = {a01.x, a01.y, a23.x, a23.y, a45.x, a45.y, a67.x, a67.y};
#pragma unroll
            for (int ii2 = 0; ii2 < 4; ii2++)
#pragma unroll
                for (int c = 0; c < 8; c++)
                    FMA2(acc2[ii2][c], xp[ii2], ap[c], acc2[ii2][c]);
        }
        __syncthreads();
    }

    // ---- dump M tile into shared (aliases Xs/As2; loop-final sync covers WAR)
#pragma unroll
    for (int ii2 = 0; ii2 < 4; ii2++) {
        float lo[8], hi[8];
#pragma unroll
        for (int c = 0; c < 8; c++) upk2(lo[c], hi[c], acc2[ii2][c]);
        int r0 = ig * 8 + 2 * ii2;
        *(float4*)&Ms[r0][klg * 8]         = make_float4(lo[0], lo[1], lo[2], lo[3]);
        *(float4*)&Ms[r0][klg * 8 + 4]     = make_float4(lo[4], lo[5], lo[6], lo[7]);
        *(float4*)&Ms[r0 + 1][klg * 8]     = make_float4(hi[0], hi[1], hi[2], hi[3]);
        *(float4*)&Ms[r0 + 1][klg * 8 + 4] = make_float4(hi[4], hi[5], hi[6], hi[7]);
    }
    __syncthreads();

    // ---- Taylor: 8 lanes per 8x8 matrix, one row per lane, 8 passes, f32x2
    const int r     = tid & 7;
    const int mbase = tid >> 3;   // 0..31

    const float invn[7] = {0.f, 1.f, 0.5f, 1.f / 3.f, 0.25f, 0.2f, 1.f / 6.f};

#pragma unroll 1
    for (int p = 0; p < 8; p++) {
        const int m = p * 32 + mbase;

        // full M, rows k, columns packed in pairs
        u64 Mg[8][4];
#pragma unroll
        for (int k = 0; k < 8; k++) {
            ulonglong2 t0 = *(const ulonglong2*)&Ms[m][k * 8];
            ulonglong2 t1 = *(const ulonglong2*)&Ms[m][k * 8 + 4];
            Mg[k][0] = t0.x; Mg[k][1] = t0.y; Mg[k][2] = t1.x; Mg[k][3] = t1.y;
        }
        // own row r: current power P and running result
        u64 P[4], res[4];
        {
            ulonglong2 t0 = *(const ulonglong2*)&Ms[m][r * 8];
            ulonglong2 t1 = *(const ulonglong2*)&Ms[m][r * 8 + 4];
            P[0] = t0.x; P[1] = t0.y; P[2] = t1.x; P[3] = t1.y;
        }
#pragma unroll
        for (int c2 = 0; c2 < 4; c2++) res[c2] = P[c2];

#pragma unroll
        for (int n = 2; n <= 6; n++) {
            float ps[8];
#pragma unroll
            for (int c2 = 0; c2 < 4; c2++) upk2(ps[2 * c2], ps[2 * c2 + 1], P[c2]);
            u64 nw[4] = {0ULL, 0ULL, 0ULL, 0ULL};
#pragma unroll
            for (int k = 0; k < 8; k++) {
                u64 s2 = pk2(ps[k], ps[k]);
#pragma unroll
                for (int c2 = 0; c2 < 4; c2++)
                    FMA2(nw[c2], s2, Mg[k][c2], nw[c2]);
            }
            uint32_t ub = __float_as_uint(invn[n]);
            u64 sc2 = (u64)ub | ((u64)ub << 32);
#pragma unroll
            for (int c2 = 0; c2 < 4; c2++) {
                MUL2(nw[c2], nw[c2], sc2);
                P[c2] = nw[c2];
                ADD2(res[c2], res[c2], nw[c2]);
            }
        }

        float fr[8];
#pragma unroll
        for (int c2 = 0; c2 < 4; c2++) upk2(fr[2 * c2], fr[2 * c2 + 1], res[c2]);
#pragma unroll
        for (int c = 0; c < 8; c++) fr[c] += (c == r) ? 1.0f : 0.0f;   // identity

        size_t off = (((size_t)b * SS + (i0 + m)) * SS + j) * 64 + (size_t)r * 8;
        *(float4*)(out + off)     = make_float4(fr[0], fr[1], fr[2], fr[3]);
        *(float4*)(out + off + 4) = make_float4(fr[4], fr[5], fr[6], fr[7]);
    }
}

extern "C" void kernel_launch(void* const* d_in, const int* in_sizes, int n_in,
                              void* d_out, int out_size)
{
    const float* x = (const float*)d_in[0];   // [4,512,512]
    const float* A = (const float*)d_in[1];   // [4,512,512,8,8]
    float* out = (float*)d_out;               // [4,512,512,8,8]
    (void)in_sizes; (void)n_in; (void)out_size;

    cudaFuncSetAttribute(pt_kernel, cudaFuncAttributeMaxDynamicSharedMemorySize, DYN_SMEM);

    dim3 grid(4 * 512 * 2);   // (b, j, i-tile), i-tile fastest
    dim3 block(THREADS);
    pt_kernel<<<grid, block, DYN_SMEM>>>(x, A, out);
}

// round 11
// speedup vs baseline: 2.5275x; 2.5203x over previous
#include <cuda_runtime.h>
#include <cstdint>

// ParallelTransport via warp-level mma.sync (TF32 x3 split) + f32x2 Taylor.
//   Per CTA (b, j, i-tile of 128):
//     M[128 i, 64 kl] = sum_d Y[i,d] * A_j[d,kl],  Y = x_j - x_i
//   Split each operand into tf32 hi+lo; accumulate Yh*Bh + Yh*Bl + Yl*Bh in
//   fp32 via mma.sync.m16n8k8. Then 6-term Taylor exp per 8x8 matrix.
//   (tcgen05 is unavailable: harness lowers via compute_103 PTX, no 'a'.)

typedef unsigned long long u64;

#define SS       512
#define DD       512
#define TILE_I   128
#define CH       32
#define NCHUNK   (DD / CH)     // 16
#define THREADS  256

#define XST2     36            // float2 per Xs row (288 B; %128 = 32 -> conflict-free frags)
#define BST2     68            // float2 per Bs row (544 B; %128 = 32)
#define MST      68            // floats per Ms row (Taylor tile)

#define XS_BYTES (TILE_I * XST2 * 8)     // 36864
#define BS_OFF   XS_BYTES
#define BS_BYTES (CH * BST2 * 8)         // 17408
#define DYN_SMEM (XS_BYTES + BS_BYTES)   // 54272  (Ms: 128*68*4 = 34816 reuses this)

// ---- f32x2 helpers (Taylor phase) ----
#define FMA2(D,A,B,C) asm("fma.rn.f32x2 %0,%1,%2,%3;" : "=l"(D) : "l"(A), "l"(B), "l"(C))
#define MUL2(D,A,B)   asm("mul.rn.f32x2 %0,%1,%2;"    : "=l"(D) : "l"(A), "l"(B))
#define ADD2(D,A,B)   asm("add.rn.f32x2 %0,%1,%2;"    : "=l"(D) : "l"(A), "l"(B))

static __device__ __forceinline__ u64 pk2(float a, float b) {
    u64 r; asm("mov.b64 %0,{%1,%2};" : "=l"(r) : "f"(a), "f"(b)); return r;
}
static __device__ __forceinline__ void upk2(float& a, float& b, u64 v) {
    asm("mov.b64 {%0,%1},%2;" : "=f"(a), "=f"(b) : "l"(v));
}
static __device__ __forceinline__ uint32_t tf32_bits(float v) {
    uint32_t r; asm("cvt.rna.tf32.f32 %0, %1;" : "=r"(r) : "f"(v)); return r;
}
static __device__ __forceinline__ void split_tf32(float v, uint32_t& h, uint32_t& l) {
    h = tf32_bits(v);
    l = tf32_bits(v - __uint_as_float(h));
}
static __device__ __forceinline__ void mma8(float c[4],
                                            uint32_t a0, uint32_t a1,
                                            uint32_t a2, uint32_t a3,
                                            uint32_t b0, uint32_t b1) {
    asm volatile(
        "mma.sync.aligned.m16n8k8.row.col.f32.tf32.tf32.f32 "
        "{%0,%1,%2,%3}, {%4,%5,%6,%7}, {%8,%9}, {%0,%1,%2,%3};"
        : "+f"(c[0]), "+f"(c[1]), "+f"(c[2]), "+f"(c[3])
        : "r"(a0), "r"(a1), "r"(a2), "r"(a3), "r"(b0), "r"(b1));
}

__global__ __launch_bounds__(THREADS, 2)
void pt_kernel(const float* __restrict__ x,
               const float* __restrict__ A,
               float* __restrict__ out)
{
    extern __shared__ __align__(16) char sm[];
    float2 (*Xs)[XST2] = reinterpret_cast<float2 (*)[XST2]>(sm);           // [i][d] (h,l)
    float2 (*Bs)[BST2] = reinterpret_cast<float2 (*)[BST2]>(sm + BS_OFF);  // [d][kl] (h,l)
    float  (*Ms)[MST]  = reinterpret_cast<float (*)[MST]>(sm);             // Taylor tile

    const int blk = blockIdx.x;
    const int it  = blk & 3;
    const int j   = (blk >> 2) & (SS - 1);
    const int b   = blk >> 11;
    const int i0  = it * TILE_I;

    const int tid = threadIdx.x;
    const int wid = tid >> 5;
    const int lid = tid & 31;
    const int grp = lid >> 2;    // 0..7
    const int thr = lid & 3;     // 0..3

    const float* xi_base = x + ((size_t)b * SS + i0) * DD;
    const float* xj      = x + ((size_t)b * SS + j) * DD;
    const float* Ab      = A + ((size_t)b * SS + j) * (size_t)DD * 64;

    // Accumulators: warp covers rows [wid*16, wid*16+16), 8 n-tiles of 8 cols
    float C[8][4];
#pragma unroll
    for (int nt = 0; nt < 8; nt++)
#pragma unroll
        for (int q = 0; q < 4; q++) C[nt][q] = 0.0f;

    for (int c = 0; c < NCHUNK; c++) {
        const int dk = c * CH;

        // ---- stage X: Y[i, dk..dk+32) split -> Xs[i][dloc] = (h,l)
#pragma unroll
        for (int f = tid; f < TILE_I * (CH / 4); f += THREADS) {   // 1024 -> 4/thr
            int row = f >> 3, q = f & 7;
            float4 vi = *(const float4*)(xi_base + (size_t)row * DD + dk + q * 4);
            float4 vj = *(const float4*)(xj + dk + q * 4);
            float y[4] = {vj.x - vi.x, vj.y - vi.y, vj.z - vi.z, vj.w - vi.w};
            uint32_t h[4], l[4];
#pragma unroll
            for (int e = 0; e < 4; e++) split_tf32(y[e], h[e], l[e]);
            uint4* dst = (uint4*)&Xs[row][q * 4];
            dst[0] = make_uint4(h[0], l[0], h[1], l[1]);
            dst[1] = make_uint4(h[2], l[2], h[3], l[3]);
        }
        // ---- stage B: A[b,j, dk+d, kl] split -> Bs[d][kl] = (h,l)
#pragma unroll
        for (int f = tid; f < CH * 16; f += THREADS) {             // 512 -> 2/thr
            int d = f >> 4, q = f & 15;
            float4 v = *(const float4*)(Ab + (size_t)(dk + d) * 64 + q * 4);
            float vv[4] = {v.x, v.y, v.z, v.w};
            uint32_t h[4], l[4];
#pragma unroll
            for (int e = 0; e < 4; e++) split_tf32(vv[e], h[e], l[e]);
            uint4* dst = (uint4*)&Bs[d][q * 4];
            dst[0] = make_uint4(h[0], l[0], h[1], l[1]);
            dst[1] = make_uint4(h[2], l[2], h[3], l[3]);
        }
        __syncthreads();

        // ---- compute: 4 k-steps of 8
#pragma unroll
        for (int ks = 0; ks < 4; ks++) {
            const int k0 = ks * 8;
            const int r0 = wid * 16 + grp;
            float2 a0 = Xs[r0][k0 + thr];
            float2 a1 = Xs[r0 + 8][k0 + thr];
            float2 a2 = Xs[r0][k0 + thr + 4];
            float2 a3 = Xs[r0 + 8][k0 + thr + 4];
            uint32_t a0h = __float_as_uint(a0.x), a0l = __float_as_uint(a0.y);
            uint32_t a1h = __float_as_uint(a1.x), a1l = __float_as_uint(a1.y);
            uint32_t a2h = __float_as_uint(a2.x), a2l = __float_as_uint(a2.y);
            uint32_t a3h = __float_as_uint(a3.x), a3l = __float_as_uint(a3.y);
#pragma unroll
            for (int nt = 0; nt < 8; nt++) {
                float2 b0 = Bs[k0 + thr][nt * 8 + grp];
                float2 b1 = Bs[k0 + thr + 4][nt * 8 + grp];
                uint32_t b0h = __float_as_uint(b0.x), b0l = __float_as_uint(b0.y);
                uint32_t b1h = __float_as_uint(b1.x), b1l = __float_as_uint(b1.y);
                mma8(C[nt], a0h, a1h, a2h, a3h, b0h, b1h);   // Yh * Bh
                mma8(C[nt], a0h, a1h, a2h, a3h, b0l, b1l);   // Yh * Bl
                mma8(C[nt], a0l, a1l, a2l, a3l, b0h, b1h);   // Yl * Bh
            }
        }
        __syncthreads();
    }

    // ---- dump M tile to shared for Taylor (sync above covers WAR on Xs/Bs)
    {
        const int r0 = wid * 16 + grp;
#pragma unroll
        for (int nt = 0; nt < 8; nt++) {
            int c0 = nt * 8 + 2 * thr;
            *(float2*)&Ms[r0][c0]     = make_float2(C[nt][0], C[nt][1]);
            *(float2*)&Ms[r0 + 8][c0] = make_float2(C[nt][2], C[nt][3]);
        }
    }
    __syncthreads();

    // ---- Taylor: 8 lanes per 8x8 matrix, one row per lane, f32x2, 4 passes
    const int r     = tid & 7;
    const int mbase = tid >> 3;   // 0..31
    const float invn[7] = {0.f, 1.f, 0.5f, 1.f / 3.f, 0.25f, 0.2f, 1.f / 6.f};

#pragma unroll 1
    for (int p = 0; p < 4; p++) {
        const int m = p * 32 + mbase;

        u64 Mg[8][4];
#pragma unroll
        for (int k = 0; k < 8; k++) {
            ulonglong2 t0 = *(const ulonglong2*)&Ms[m][k * 8];
            ulonglong2 t1 = *(const ulonglong2*)&Ms[m][k * 8 + 4];
            Mg[k][0] = t0.x; Mg[k][1] = t0.y; Mg[k][2] = t1.x; Mg[k][3] = t1.y;
        }
        u64 P[4], res[4];
        {
            ulonglong2 t0 = *(const ulonglong2*)&Ms[m][r * 8];
            ulonglong2 t1 = *(const ulonglong2*)&Ms[m][r * 8 + 4];
            P[0] = t0.x; P[1] = t0.y; P[2] = t1.x; P[3] = t1.y;
        }
#pragma unroll
        for (int c2 = 0; c2 < 4; c2++) res[c2] = P[c2];

#pragma unroll
        for (int n = 2; n <= 6; n++) {
            float ps[8];
#pragma unroll
            for (int c2 = 0; c2 < 4; c2++) upk2(ps[2 * c2], ps[2 * c2 + 1], P[c2]);
            u64 nw[4] = {0ULL, 0ULL, 0ULL, 0ULL};
#pragma unroll
            for (int k = 0; k < 8; k++) {
                u64 s2 = pk2(ps[k], ps[k]);
#pragma unroll
                for (int c2 = 0; c2 < 4; c2++)
                    FMA2(nw[c2], s2, Mg[k][c2], nw[c2]);
            }
            uint32_t ub = __float_as_uint(invn[n]);
            u64 sc2 = (u64)ub | ((u64)ub << 32);
#pragma unroll
            for (int c2 = 0; c2 < 4; c2++) {
                MUL2(nw[c2], nw[c2], sc2);
                P[c2] = nw[c2];
                ADD2(res[c2], res[c2], nw[c2]);
            }
        }

        float fr[8];
#pragma unroll
        for (int c2 = 0; c2 < 4; c2++) upk2(fr[2 * c2], fr[2 * c2 + 1], res[c2]);
#pragma unroll
        for (int cc = 0; cc < 8; cc++) fr[cc] += (cc == r) ? 1.0f : 0.0f;

        size_t off = (((size_t)b * SS + (i0 + m)) * SS + j) * 64 + (size_t)r * 8;
        *(float4*)(out + off)     = make_float4(fr[0], fr[1], fr[2], fr[3]);
        *(float4*)(out + off + 4) = make_float4(fr[4], fr[5], fr[6], fr[7]);
    }
}

extern "C" void kernel_launch(void* const* d_in, const int* in_sizes, int n_in,
                              void* d_out, int out_size)
{
    const float* x = (const float*)d_in[0];   // [4,512,512]
    const float* A = (const float*)d_in[1];   // [4,512,512,8,8]
    float* out = (float*)d_out;               // [4,512,512,8,8]
    (void)in_sizes; (void)n_in; (void)out_size;

    cudaFuncSetAttribute(pt_kernel, cudaFuncAttributeMaxDynamicSharedMemorySize, DYN_SMEM);

    dim3 grid(4 * 512 * 4);   // (b, j, i-tile), i-tile fastest
    dim3 block(THREADS);
    pt_kernel<<<grid, block, DYN_SMEM>>>(x, A, out);
}

// round 12
// speedup vs baseline: 2.5295x; 1.0008x over previous
#include <cuda_runtime.h>
#include <cstdint>

// ParallelTransport via warp-level mma.sync (TF32 x3 split) + f32x2 Taylor.
//   Per CTA (b, j, i-tile of 128):
//     M[128 i, 64 kl] = sum_d Y[i,d] * A_j[d,kl],  Y = x_j - x_i
//   Split each operand into tf32 hi+lo; accumulate Yh*Bh + Yh*Bl + Yl*Bh in
//   fp32 via mma.sync.m16n8k8. Then 6-term Taylor exp per 8x8 matrix.
//   (tcgen05 is unavailable: harness lowers via compute_103 PTX, no 'a'.)

typedef unsigned long long u64;

#define SS       512
#define DD       512
#define TILE_I   128
#define CH       32
#define NCHUNK   (DD / CH)     // 16
#define THREADS  256

#define XST2     36            // float2 per Xs row (288 B; %128 = 32 -> conflict-free frags)
#define BST2     68            // float2 per Bs row (544 B; %128 = 32)
#define MST      68            // floats per Ms row (Taylor tile)

#define XS_BYTES (TILE_I * XST2 * 8)     // 36864
#define BS_OFF   XS_BYTES
#define BS_BYTES (CH * BST2 * 8)         // 17408
#define DYN_SMEM (XS_BYTES + BS_BYTES)   // 54272  (Ms: 128*68*4 = 34816 reuses this)

// ---- f32x2 helpers (Taylor phase) ----
#define FMA2(D,A,B,C) asm("fma.rn.f32x2 %0,%1,%2,%3;" : "=l"(D) : "l"(A), "l"(B), "l"(C))
#define MUL2(D,A,B)   asm("mul.rn.f32x2 %0,%1,%2;"    : "=l"(D) : "l"(A), "l"(B))
#define ADD2(D,A,B)   asm("add.rn.f32x2 %0,%1,%2;"    : "=l"(D) : "l"(A), "l"(B))

static __device__ __forceinline__ u64 pk2(float a, float b) {
    u64 r; asm("mov.b64 %0,{%1,%2};" : "=l"(r) : "f"(a), "f"(b)); return r;
}
static __device__ __forceinline__ void upk2(float& a, float& b, u64 v) {
    asm("mov.b64 {%0,%1},%2;" : "=f"(a), "=f"(b) : "l"(v));
}
static __device__ __forceinline__ uint32_t tf32_bits(float v) {
    uint32_t r; asm("cvt.rna.tf32.f32 %0, %1;" : "=r"(r) : "f"(v)); return r;
}
static __device__ __forceinline__ void split_tf32(float v, uint32_t& h, uint32_t& l) {
    h = tf32_bits(v);
    l = tf32_bits(v - __uint_as_float(h));
}
static __device__ __forceinline__ void mma8(float c[4],
                                            uint32_t a0, uint32_t a1,
                                            uint32_t a2, uint32_t a3,
                                            uint32_t b0, uint32_t b1) {
    asm volatile(
        "mma.sync.aligned.m16n8k8.row.col.f32.tf32.tf32.f32 "
        "{%0,%1,%2,%3}, {%4,%5,%6,%7}, {%8,%9}, {%0,%1,%2,%3};"
        : "+f"(c[0]), "+f"(c[1]), "+f"(c[2]), "+f"(c[3])
        : "r"(a0), "r"(a1), "r"(a2), "r"(a3), "r"(b0), "r"(b1));
}

__global__ __launch_bounds__(THREADS, 2)
void pt_kernel(const float* __restrict__ x,
               const float* __restrict__ A,
               float* __restrict__ out)
{
    extern __shared__ __align__(16) char sm[];
    float2 (*Xs)[XST2] = reinterpret_cast<float2 (*)[XST2]>(sm);           // [i][d] (h,l)
    float2 (*Bs)[BST2] = reinterpret_cast<float2 (*)[BST2]>(sm + BS_OFF);  // [d][kl] (h,l)
    float  (*Ms)[MST]  = reinterpret_cast<float (*)[MST]>(sm);             // Taylor tile

    const int blk = blockIdx.x;
    const int it  = blk & 3;
    const int j   = (blk >> 2) & (SS - 1);
    const int b   = blk >> 11;
    const int i0  = it * TILE_I;

    const int tid = threadIdx.x;
    const int wid = tid >> 5;
    const int lid = tid & 31;
    const int grp = lid >> 2;    // 0..7
    const int thr = lid & 3;     // 0..3

    const float* xi_base = x + ((size_t)b * SS + i0) * DD;
    const float* xj      = x + ((size_t)b * SS + j) * DD;
    const float* Ab      = A + ((size_t)b * SS + j) * (size_t)DD * 64;

    // Accumulators: warp covers rows [wid*16, wid*16+16), 8 n-tiles of 8 cols
    float C[8][4];
#pragma unroll
    for (int nt = 0; nt < 8; nt++)
#pragma unroll
        for (int q = 0; q < 4; q++) C[nt][q] = 0.0f;

    for (int c = 0; c < NCHUNK; c++) {
        const int dk = c * CH;

        // ---- stage X: Y[i, dk..dk+32) split -> Xs[i][dloc] = (h,l)
#pragma unroll
        for (int f = tid; f < TILE_I * (CH / 4); f += THREADS) {   // 1024 -> 4/thr
            int row = f >> 3, q = f & 7;
            float4 vi = *(const float4*)(xi_base + (size_t)row * DD + dk + q * 4);
            float4 vj = *(const float4*)(xj + dk + q * 4);
            float y[4] = {vj.x - vi.x, vj.y - vi.y, vj.z - vi.z, vj.w - vi.w};
            uint32_t h[4], l[4];
#pragma unroll
            for (int e = 0; e < 4; e++) split_tf32(y[e], h[e], l[e]);
            uint4* dst = (uint4*)&Xs[row][q * 4];
            dst[0] = make_uint4(h[0], l[0], h[1], l[1]);
            dst[1] = make_uint4(h[2], l[2], h[3], l[3]);
        }
        // ---- stage B: A[b,j, dk+d, kl] split -> Bs[d][kl] = (h,l)
#pragma unroll
        for (int f = tid; f < CH * 16; f += THREADS) {             // 512 -> 2/thr
            int d = f >> 4, q = f & 15;
            float4 v = *(const float4*)(Ab + (size_t)(dk + d) * 64 + q * 4);
            float vv[4] = {v.x, v.y, v.z, v.w};
            uint32_t h[4], l[4];
#pragma unroll
            for (int e = 0; e < 4; e++) split_tf32(vv[e], h[e], l[e]);
            uint4* dst = (uint4*)&Bs[d][q * 4];
            dst[0] = make_uint4(h[0], l[0], h[1], l[1]);
            dst[1] = make_uint4(h[2], l[2], h[3], l[3]);
        }
        __syncthreads();

        // ---- compute: 4 k-steps of 8
#pragma unroll
        for (int ks = 0; ks < 4; ks++) {
            const int k0 = ks * 8;
            const int r0 = wid * 16 + grp;
            float2 a0 = Xs[r0][k0 + thr];
            float2 a1 = Xs[r0 + 8][k0 + thr];
            float2 a2 = Xs[r0][k0 + thr + 4];
            float2 a3 = Xs[r0 + 8][k0 + thr + 4];
            uint32_t a0h = __float_as_uint(a0.x), a0l = __float_as_uint(a0.y);
            uint32_t a1h = __float_as_uint(a1.x), a1l = __float_as_uint(a1.y);
            uint32_t a2h = __float_as_uint(a2.x), a2l = __float_as_uint(a2.y);
            uint32_t a3h = __float_as_uint(a3.x), a3l = __float_as_uint(a3.y);
#pragma unroll
            for (int nt = 0; nt < 8; nt++) {
                float2 b0 = Bs[k0 + thr][nt * 8 + grp];
                float2 b1 = Bs[k0 + thr + 4][nt * 8 + grp];
                uint32_t b0h = __float_as_uint(b0.x), b0l = __float_as_uint(b0.y);
                uint32_t b1h = __float_as_uint(b1.x), b1l = __float_as_uint(b1.y);
                mma8(C[nt], a0h, a1h, a2h, a3h, b0h, b1h);   // Yh * Bh
                mma8(C[nt], a0h, a1h, a2h, a3h, b0l, b1l);   // Yh * Bl
                mma8(C[nt], a0l, a1l, a2l, a3l, b0h, b1h);   // Yl * Bh
            }
        }
        __syncthreads();
    }

    // ---- dump M tile to shared for Taylor (sync above covers WAR on Xs/Bs)
    {
        const int r0 = wid * 16 + grp;
#pragma unroll
        for (int nt = 0; nt < 8; nt++) {
            int c0 = nt * 8 + 2 * thr;
            *(float2*)&Ms[r0][c0]     = make_float2(C[nt][0], C[nt][1]);
            *(float2*)&Ms[r0 + 8][c0] = make_float2(C[nt][2], C[nt][3]);
        }
    }
    __syncthreads();

    // ---- Taylor: 8 lanes per 8x8 matrix, one row per lane, f32x2, 4 passes
    const int r     = tid & 7;
    const int mbase = tid >> 3;   // 0..31
    const float invn[7] = {0.f, 1.f, 0.5f, 1.f / 3.f, 0.25f, 0.2f, 1.f / 6.f};

#pragma unroll 1
    for (int p = 0; p < 4; p++) {
        const int m = p * 32 + mbase;

        u64 Mg[8][4];
#pragma unroll
        for (int k = 0; k < 8; k++) {
            ulonglong2 t0 = *(const ulonglong2*)&Ms[m][k * 8];
            ulonglong2 t1 = *(const ulonglong2*)&Ms[m][k * 8 + 4];
            Mg[k][0] = t0.x; Mg[k][1] = t0.y; Mg[k][2] = t1.x; Mg[k][3] = t1.y;
        }
        u64 P[4], res[4];
        {
            ulonglong2 t0 = *(const ulonglong2*)&Ms[m][r * 8];
            ulonglong2 t1 = *(const ulonglong2*)&Ms[m][r * 8 + 4];
            P[0] = t0.x; P[1] = t0.y; P[2] = t1.x; P[3] = t1.y;
        }
#pragma unroll
        for (int c2 = 0; c2 < 4; c2++) res[c2] = P[c2];

#pragma unroll
        for (int n = 2; n <= 6; n++) {
            float ps[8];
#pragma unroll
            for (int c2 = 0; c2 < 4; c2++) upk2(ps[2 * c2], ps[2 * c2 + 1], P[c2]);
            u64 nw[4] = {0ULL, 0ULL, 0ULL, 0ULL};
#pragma unroll
            for (int k = 0; k < 8; k++) {
                u64 s2 = pk2(ps[k], ps[k]);
#pragma unroll
                for (int c2 = 0; c2 < 4; c2++)
                    FMA2(nw[c2], s2, Mg[k][c2], nw[c2]);
            }
            uint32_t ub = __float_as_uint(invn[n]);
            u64 sc2 = (u64)ub | ((u64)ub << 32);
#pragma unroll
            for (int c2 = 0; c2 < 4; c2++) {
                MUL2(nw[c2], nw[c2], sc2);
                P[c2] = nw[c2];
                ADD2(res[c2], res[c2], nw[c2]);
            }
        }

        float fr[8];
#pragma unroll
        for (int c2 = 0; c2 < 4; c2++) upk2(fr[2 * c2], fr[2 * c2 + 1], res[c2]);
#pragma unroll
        for (int cc = 0; cc < 8; cc++) fr[cc] += (cc == r) ? 1.0f : 0.0f;

        size_t off = (((size_t)b * SS + (i0 + m)) * SS + j) * 64 + (size_t)r * 8;
        *(float4*)(out + off)     = make_float4(fr[0], fr[1], fr[2], fr[3]);
        *(float4*)(out + off + 4) = make_float4(fr[4], fr[5], fr[6], fr[7]);
    }
}

extern "C" void kernel_launch(void* const* d_in, const int* in_sizes, int n_in,
                              void* d_out, int out_size)
{
    const float* x = (const float*)d_in[0];   // [4,512,512]
    const float* A = (const float*)d_in[1];   // [4,512,512,8,8]
    float* out = (float*)d_out;               // [4,512,512,8,8]
    (void)in_sizes; (void)n_in; (void)out_size;

    cudaFuncSetAttribute(pt_kernel, cudaFuncAttributeMaxDynamicSharedMemorySize, DYN_SMEM);

    dim3 grid(4 * 512 * 4);   // (b, j, i-tile), i-tile fastest
    dim3 block(THREADS);
    pt_kernel<<<grid, block, DYN_SMEM>>>(x, A, out);
}

// round 13
// speedup vs baseline: 5.1121x; 2.0210x over previous
#include <cuda_runtime.h>
#include <cstdint>

// ParallelTransport, R13: bf16x3 mma.sync + precomputed split operands.
//   M[b,i,j,:,:] = G[b,j,:,:] - L,  L = sum_d x[b,i,d]*A[b,j,d,:,:]
//   G[b,j,kl]    = sum_d x[b,j,d]*A[b,j,d,kl]   (f32, prep kernel)
//   L via mma.sync.m16n8k16 bf16, 3-pass split (h*h + h*l + l*h), fp32 accum.
//   A and x pre-split into bf16 hi/lo planes in __device__ scratch; A stored
//   transposed [b][j][kl][d] so main-kernel staging is pure cp.async copy.
// Then 6-term Taylor exp per 8x8 matrix (f32x2).

typedef unsigned long long u64;

#define SS 512
#define DD 512

// ---- global scratch (device statics; no allocs allowed) ----
__device__ uint16_t g_Xh[4 * SS * DD];                    // [b*512+i][d] bf16
__device__ uint16_t g_Xl[4 * SS * DD];
__device__ uint16_t g_Ah[(size_t)4 * SS * 64 * DD];       // [b*512+j][kl][d] bf16
__device__ uint16_t g_Al[(size_t)4 * SS * 64 * DD];
__device__ float    g_G [4 * SS * 64];                    // [b*512+j][kl]

// ---- main-kernel smem layout (bytes) ----
#define XROW_B   144                 // 72 bf16 stride (conflict-free frags)
#define SXH_OFF  0
#define SXL_OFF  (128 * XROW_B)      // 18432
#define SBH_OFF  (2 * 128 * XROW_B)  // 36864
#define SBL_OFF  (SBH_OFF + 64 * XROW_B)   // 46080
#define DYN_SMEM (SBL_OFF + 64 * XROW_B)   // 55296
#define MST      68                  // floats per Ms row (Taylor tile)

// ---- f32x2 helpers (Taylor) ----
#define FMA2(D,A,B,C) asm("fma.rn.f32x2 %0,%1,%2,%3;" : "=l"(D) : "l"(A), "l"(B), "l"(C))
#define MUL2(D,A,B)   asm("mul.rn.f32x2 %0,%1,%2;"    : "=l"(D) : "l"(A), "l"(B))
#define ADD2(D,A,B)   asm("add.rn.f32x2 %0,%1,%2;"    : "=l"(D) : "l"(A), "l"(B))

static __device__ __forceinline__ u64 pk2(float a, float b) {
    u64 r; asm("mov.b64 %0,{%1,%2};" : "=l"(r) : "f"(a), "f"(b)); return r;
}
static __device__ __forceinline__ void upk2(float& a, float& b, u64 v) {
    asm("mov.b64 {%0,%1},%2;" : "=f"(a), "=f"(b) : "l"(v));
}

// ---- bf16 split ----
static __device__ __forceinline__ void split_bf(float v, uint16_t& h, uint16_t& l) {
    unsigned short hh;
    asm("cvt.rn.bf16.f32 %0, %1;" : "=h"(hh) : "f"(v));
    float hf = __uint_as_float((uint32_t)hh << 16);
    unsigned short ll;
    asm("cvt.rn.bf16.f32 %0, %1;" : "=h"(ll) : "f"(v - hf));
    h = hh; l = ll;
}

// ---- misc PTX ----
static __device__ __forceinline__ uint32_t smem_u32(const void* p) {
    uint32_t a;
    asm("{.reg .u64 t; cvta.to.shared.u64 t, %1; cvt.u32.u64 %0, t;}" : "=r"(a) : "l"(p));
    return a;
}
static __device__ __forceinline__ void cp16(uint32_t dst, const void* src) {
    asm volatile("cp.async.cg.shared.global [%0], [%1], 16;" :: "r"(dst), "l"(src) : "memory");
}
#define CP_COMMIT() asm volatile("cp.async.commit_group;" ::: "memory")
#define CP_WAIT0()  asm volatile("cp.async.wait_group 0;" ::: "memory")

static __device__ __forceinline__ void mma16(float c[4], const uint32_t a[4],
                                             uint32_t b0, uint32_t b1) {
    asm volatile(
        "mma.sync.aligned.m16n8k16.row.col.f32.bf16.bf16.f32 "
        "{%0,%1,%2,%3}, {%4,%5,%6,%7}, {%8,%9}, {%0,%1,%2,%3};"
        : "+f"(c[0]), "+f"(c[1]), "+f"(c[2]), "+f"(c[3])
        : "r"(a[0]), "r"(a[1]), "r"(a[2]), "r"(a[3]), "r"(b0), "r"(b1));
}

// ================= prep kernels =================

__global__ void prep_x(const float* __restrict__ x)
{
    int f = blockIdx.x * 256 + threadIdx.x;          // 262144 threads, 4 elems each
    float4 v = *(const float4*)(x + (size_t)f * 4);
    uint16_t h[4], l[4];
    split_bf(v.x, h[0], l[0]); split_bf(v.y, h[1], l[1]);
    split_bf(v.z, h[2], l[2]); split_bf(v.w, h[3], l[3]);
    uint2 hu, lu;
    hu.x = (uint32_t)h[0] | ((uint32_t)h[1] << 16);
    hu.y = (uint32_t)h[2] | ((uint32_t)h[3] << 16);
    lu.x = (uint32_t)l[0] | ((uint32_t)l[1] << 16);
    lu.y = (uint32_t)l[2] | ((uint32_t)l[3] << 16);
    *(uint2*)(g_Xh + (size_t)f * 4) = hu;
    *(uint2*)(g_Xl + (size_t)f * 4) = lu;
}

__global__ void prep_a(const float* __restrict__ x, const float* __restrict__ A)
{
    const int bj = blockIdx.x;                       // (b*512 + j)
    const int tid = threadIdx.x;
    const int kl  = tid >> 2;                        // 0..63
    const int sub = tid & 3;                         // 0..3 (d sub-range)

    __shared__ float xrow[DD];
    __shared__ float sgp[64][5];

    xrow[tid]       = x[(size_t)bj * DD + tid];
    xrow[tid + 256] = x[(size_t)bj * DD + tid + 256];
    __syncthreads();

    const float* Ab = A + (size_t)bj * DD * 64;
    uint16_t* Oh = g_Ah + (size_t)bj * 64 * DD + (size_t)kl * DD;
    uint16_t* Ol = g_Al + (size_t)bj * 64 * DD + (size_t)kl * DD;

    float g = 0.0f;
#pragma unroll 1
    for (int c = 0; c < 8; c++) {
        const int d0 = c * 64 + sub * 16;
        uint16_t hb[16], lb[16];
#pragma unroll
        for (int i = 0; i < 16; i++) {
            float v = __ldg(Ab + (size_t)(d0 + i) * 64 + kl);
            g = fmaf(xrow[d0 + i], v, g);
            split_bf(v, hb[i], lb[i]);
        }
        uint4 u;
        u.x = (uint32_t)hb[0]  | ((uint32_t)hb[1]  << 16);
        u.y = (uint32_t)hb[2]  | ((uint32_t)hb[3]  << 16);
        u.z = (uint32_t)hb[4]  | ((uint32_t)hb[5]  << 16);
        u.w = (uint32_t)hb[6]  | ((uint32_t)hb[7]  << 16);
        *(uint4*)(Oh + d0) = u;
        u.x = (uint32_t)hb[8]  | ((uint32_t)hb[9]  << 16);
        u.y = (uint32_t)hb[10] | ((uint32_t)hb[11] << 16);
        u.z = (uint32_t)hb[12] | ((uint32_t)hb[13] << 16);
        u.w = (uint32_t)hb[14] | ((uint32_t)hb[15] << 16);
        *(uint4*)(Oh + d0 + 8) = u;
        u.x = (uint32_t)lb[0]  | ((uint32_t)lb[1]  << 16);
        u.y = (uint32_t)lb[2]  | ((uint32_t)lb[3]  << 16);
        u.z = (uint32_t)lb[4]  | ((uint32_t)lb[5]  << 16);
        u.w = (uint32_t)lb[6]  | ((uint32_t)lb[7]  << 16);
        *(uint4*)(Ol + d0) = u;
        u.x = (uint32_t)lb[8]  | ((uint32_t)lb[9]  << 16);
        u.y = (uint32_t)lb[10] | ((uint32_t)lb[11] << 16);
        u.z = (uint32_t)lb[12] | ((uint32_t)lb[13] << 16);
        u.w = (uint32_t)lb[14] | ((uint32_t)lb[15] << 16);
        *(uint4*)(Ol + d0 + 8) = u;
    }
    sgp[kl][sub] = g;
    __syncthreads();
    if (tid < 64)
        g_G[(size_t)bj * 64 + tid] =
            (sgp[tid][0] + sgp[tid][1]) + (sgp[tid][2] + sgp[tid][3]);
}

// ================= main kernel =================

__global__ __launch_bounds__(256, 2)
void pt_main(float* __restrict__ out)
{
    extern __shared__ __align__(16) char sm[];
    const uint32_t sb = smem_u32(sm);
    uint16_t* sXh = (uint16_t*)(sm + SXH_OFF);   // [128][72]
    uint16_t* sXl = (uint16_t*)(sm + SXL_OFF);
    uint16_t* sBh = (uint16_t*)(sm + SBH_OFF);   // [64][72]
    uint16_t* sBl = (uint16_t*)(sm + SBL_OFF);
    float (*Ms)[MST] = (float (*)[MST])sm;       // Taylor tile (reuses X region)

    const int blk = blockIdx.x;
    const int it  = blk & 3;
    const int j   = (blk >> 2) & (SS - 1);
    const int b   = blk >> 11;
    const int i0  = it * 128;

    const int tid = threadIdx.x;
    const int wid = tid >> 5;
    const int lid = tid & 31;
    const int wm  = wid & 3;          // 0..3: rows wm*32
    const int wn  = wid >> 2;         // 0..1: cols wn*32
    const int g   = lid >> 2;         // 0..7
    const int t   = lid & 3;          // 0..3

    const uint16_t* Xh = g_Xh + ((size_t)b * SS + i0) * DD;
    const uint16_t* Xl = g_Xl + ((size_t)b * SS + i0) * DD;
    const uint16_t* Ahp = g_Ah + (size_t)(b * SS + j) * 64 * DD;
    const uint16_t* Alp = g_Al + (size_t)(b * SS + j) * 64 * DD;

    float C[2][4][4];
#pragma unroll
    for (int mf = 0; mf < 2; mf++)
#pragma unroll
        for (int nt = 0; nt < 4; nt++)
#pragma unroll
            for (int q = 0; q < 4; q++) C[mf][nt][q] = 0.0f;

#pragma unroll 1
    for (int cch = 0; cch < 8; cch++) {
        const int dk = cch * 64;

        // ---- stage (pure copies, 16B cp.async) ----
#pragma unroll
        for (int f = tid; f < 1024; f += 256) {        // X: 128 rows x 128B x2
            int row = f >> 3, q = f & 7;
            cp16(sb + SXH_OFF + row * XROW_B + q * 16,
                 Xh + (size_t)row * DD + dk + q * 8);
            cp16(sb + SXL_OFF + row * XROW_B + q * 16,
                 Xl + (size_t)row * DD + dk + q * 8);
        }
#pragma unroll
        for (int f = tid; f < 512; f += 256) {         // B: 64 rows x 128B x2
            int row = f >> 3, q = f & 7;
            cp16(sb + SBH_OFF + row * XROW_B + q * 16,
                 Ahp + (size_t)row * DD + dk + q * 8);
            cp16(sb + SBL_OFF + row * XROW_B + q * 16,
                 Alp + (size_t)row * DD + dk + q * 8);
        }
        CP_COMMIT(); CP_WAIT0();
        __syncthreads();

        // ---- compute: 4 k-steps of 16 ----
#pragma unroll
        for (int ks = 0; ks < 4; ks++) {
            const int k0 = ks * 16;
            uint32_t ah[2][4], al[2][4];
#pragma unroll
            for (int mf = 0; mf < 2; mf++) {
                int r0 = wm * 32 + mf * 16 + g;
                const uint16_t* p = sXh + r0 * 72 + k0 + 2 * t;
                ah[mf][0] = *(const uint32_t*)p;
                ah[mf][1] = *(const uint32_t*)(p + 8 * 72);
                ah[mf][2] = *(const uint32_t*)(p + 8);
                ah[mf][3] = *(const uint32_t*)(p + 8 * 72 + 8);
                const uint16_t* pl = sXl + r0 * 72 + k0 + 2 * t;
                al[mf][0] = *(const uint32_t*)pl;
                al[mf][1] = *(const uint32_t*)(pl + 8 * 72);
                al[mf][2] = *(const uint32_t*)(pl + 8);
                al[mf][3] = *(const uint32_t*)(pl + 8 * 72 + 8);
            }
#pragma unroll
            for (int nt = 0; nt < 4; nt++) {
                int n = wn * 32 + nt * 8 + g;
                const uint16_t* q = sBh + n * 72 + k0 + 2 * t;
                uint32_t bh0 = *(const uint32_t*)q;
                uint32_t bh1 = *(const uint32_t*)(q + 8);
                const uint16_t* ql = sBl + n * 72 + k0 + 2 * t;
                uint32_t bl0 = *(const uint32_t*)ql;
                uint32_t bl1 = *(const uint32_t*)(ql + 8);
#pragma unroll
                for (int mf = 0; mf < 2; mf++) {
                    mma16(C[mf][nt], ah[mf], bh0, bh1);   // h*h
                    mma16(C[mf][nt], ah[mf], bl0, bl1);   // h*l
                    mma16(C[mf][nt], al[mf], bh0, bh1);   // l*h
                }
            }
        }
        __syncthreads();
    }

    // ---- epilogue: Ms = G - L ----
    const float* Gp = g_G + (size_t)(b * SS + j) * 64;
#pragma unroll
    for (int nt = 0; nt < 4; nt++) {
        int c = wn * 32 + nt * 8 + 2 * t;
        float2 gv = *(const float2*)(Gp + c);
#pragma unroll
        for (int mf = 0; mf < 2; mf++) {
            int r = wm * 32 + mf * 16 + g;
            *(float2*)&Ms[r][c]     = make_float2(gv.x - C[mf][nt][0],
                                                  gv.y - C[mf][nt][1]);
            *(float2*)&Ms[r + 8][c] = make_float2(gv.x - C[mf][nt][2],
                                                  gv.y - C[mf][nt][3]);
        }
    }
    __syncthreads();

    // ---- Taylor: 8 lanes per 8x8 matrix, f32x2, 4 passes ----
    const int r     = tid & 7;
    const int mbase = tid >> 3;   // 0..31
    const float invn[7] = {0.f, 1.f, 0.5f, 1.f / 3.f, 0.25f, 0.2f, 1.f / 6.f};

#pragma unroll 1
    for (int p = 0; p < 4; p++) {
        const int m = p * 32 + mbase;

        u64 Mg[8][4];
#pragma unroll
        for (int k = 0; k < 8; k++) {
            ulonglong2 t0 = *(const ulonglong2*)&Ms[m][k * 8];
            ulonglong2 t1 = *(const ulonglong2*)&Ms[m][k * 8 + 4];
            Mg[k][0] = t0.x; Mg[k][1] = t0.y; Mg[k][2] = t1.x; Mg[k][3] = t1.y;
        }
        u64 P[4], res[4];
        {
            ulonglong2 t0 = *(const ulonglong2*)&Ms[m][r * 8];
            ulonglong2 t1 = *(const ulonglong2*)&Ms[m][r * 8 + 4];
            P[0] = t0.x; P[1] = t0.y; P[2] = t1.x; P[3] = t1.y;
        }
#pragma unroll
        for (int c2 = 0; c2 < 4; c2++) res[c2] = P[c2];

#pragma unroll
        for (int n = 2; n <= 6; n++) {
            float ps[8];
#pragma unroll
            for (int c2 = 0; c2 < 4; c2++) upk2(ps[2 * c2], ps[2 * c2 + 1], P[c2]);
            u64 nw[4] = {0ULL, 0ULL, 0ULL, 0ULL};
#pragma unroll
            for (int k = 0; k < 8; k++) {
                u64 s2 = pk2(ps[k], ps[k]);
#pragma unroll
                for (int c2 = 0; c2 < 4; c2++)
                    FMA2(nw[c2], s2, Mg[k][c2], nw[c2]);
            }
            uint32_t ub = __float_as_uint(invn[n]);
            u64 sc2 = (u64)ub | ((u64)ub << 32);
#pragma unroll
            for (int c2 = 0; c2 < 4; c2++) {
                MUL2(nw[c2], nw[c2], sc2);
                P[c2] = nw[c2];
                ADD2(res[c2], res[c2], nw[c2]);
            }
        }

        float fr[8];
#pragma unroll
        for (int c2 = 0; c2 < 4; c2++) upk2(fr[2 * c2], fr[2 * c2 + 1], res[c2]);
#pragma unroll
        for (int cc = 0; cc < 8; cc++) fr[cc] += (cc == r) ? 1.0f : 0.0f;

        size_t off = (((size_t)b * SS + (i0 + m)) * SS + j) * 64 + (size_t)r * 8;
        *(float4*)(out + off)     = make_float4(fr[0], fr[1], fr[2], fr[3]);
        *(float4*)(out + off + 4) = make_float4(fr[4], fr[5], fr[6], fr[7]);
    }
}

// ================= launcher =================

extern "C" void kernel_launch(void* const* d_in, const int* in_sizes, int n_in,
                              void* d_out, int out_size)
{
    const float* x = (const float*)d_in[0];   // [4,512,512]
    const float* A = (const float*)d_in[1];   // [4,512,512,8,8]
    float* out = (float*)d_out;               // [4,512,512,8,8]
    (void)in_sizes; (void)n_in; (void)out_size;

    cudaFuncSetAttribute(pt_main, cudaFuncAttributeMaxDynamicSharedMemorySize, DYN_SMEM);

    prep_x<<<1024, 256>>>(x);
    prep_a<<<4 * SS, 256>>>(x, A);
    pt_main<<<4 * SS * 4, 256, DYN_SMEM>>>(out);
}